// round 12
// baseline (speedup 1.0000x reference)
#include <cuda_runtime.h>
#include <cuda_bf16.h>
#include <cstdint>

#define NB 4
#define NT 1024
#define NC 768
#define NH 12
#define ND 64

// ---------------- scratch (device globals; no allocation allowed) ----------
// bf16 split operands
__device__ __nv_bfloat16 g_xh[4096*768],  g_xl[4096*768];
__device__ __nv_bfloat16 g_wqh[2304*768], g_wql[2304*768];   // W_qkv^T  [N][K]
__device__ __nv_bfloat16 g_wph[768*768],  g_wpl[768*768];    // W_proj^T [N][K]
__device__ __nv_bfloat16 g_yhh[4096*768], g_yhl[4096*768];   // y pre-proj hi/lo
// q,k: [b,h,t,d]; v transposed: [b,h,d,s]
__device__ __nv_bfloat16 g_qh[NB*NH*NT*ND], g_ql[NB*NH*NT*ND];
__device__ __nv_bfloat16 g_kh[NB*NH*NT*ND], g_kl[NB*NH*NT*ND];
__device__ __nv_bfloat16 g_vth[NB*NH*ND*NT], g_vtl[NB*NH*ND*NT];

// ===================== HMMA helpers (sm_80+ portable) ======================
__device__ __forceinline__ uint32_t smem_u32(const void* p) {
    uint32_t a;
    asm("{ .reg .u64 t; cvta.to.shared.u64 t, %1; cvt.u32.u64 %0, t; }" : "=r"(a) : "l"(p));
    return a;
}
__device__ __forceinline__ void ldsm4(uint32_t* r, uint32_t addr) {
    asm volatile("ldmatrix.sync.aligned.m8n8.x4.shared.b16 {%0,%1,%2,%3}, [%4];"
        : "=r"(r[0]), "=r"(r[1]), "=r"(r[2]), "=r"(r[3]) : "r"(addr));
}
__device__ __forceinline__ void ldsm2(uint32_t* r, uint32_t addr) {
    asm volatile("ldmatrix.sync.aligned.m8n8.x2.shared.b16 {%0,%1}, [%2];"
        : "=r"(r[0]), "=r"(r[1]) : "r"(addr));
}
__device__ __forceinline__ void mma16816(float* c, const uint32_t* a, const uint32_t* b) {
    asm volatile("mma.sync.aligned.m16n8k16.row.col.f32.bf16.bf16.f32 "
        "{%0,%1,%2,%3}, {%4,%5,%6,%7}, {%8,%9}, {%0,%1,%2,%3};"
        : "+f"(c[0]), "+f"(c[1]), "+f"(c[2]), "+f"(c[3])
        : "r"(a[0]), "r"(a[1]), "r"(a[2]), "r"(a[3]), "r"(b[0]), "r"(b[1]));
}
__device__ __forceinline__ void cpasync16(uint32_t dst, const void* src) {
    asm volatile("cp.async.cg.shared.global [%0], [%1], 16;" :: "r"(dst), "l"(src));
}
#define CP_COMMIT() asm volatile("cp.async.commit_group;" ::: "memory")

// pack two fp32 -> bf16x2 (lo in low half)
__device__ __forceinline__ uint32_t pkbf2(float lo, float hi) {
    uint32_t r;
    asm("cvt.rn.bf16x2.f32 %0, %1, %2;" : "=r"(r) : "f"(hi), "f"(lo));
    return r;
}

// fast exp2: magic round + deg-5 poly; t must be >= -126 (clamped by caller)
__device__ __forceinline__ float fexp2(float t) {
    const float magic = 12582912.0f;   // 1.5 * 2^23
    float r = t + magic;
    float f = t - (r - magic);
    float p = 0.00133335581f;
    p = fmaf(p, f, 0.00961812911f);
    p = fmaf(p, f, 0.0555041087f);
    p = fmaf(p, f, 0.240226507f);
    p = fmaf(p, f, 0.693147182f);
    p = fmaf(p, f, 1.0f);
    return __int_as_float(__float_as_int(p) + (__float_as_int(r) << 23));
}

// ---------------- split fp32 -> bf16 hi/lo (elementwise) -------------------
__global__ __launch_bounds__(256)
void k_split(const float* __restrict__ in, __nv_bfloat16* __restrict__ oh,
             __nv_bfloat16* __restrict__ ol)
{
    const int i = (blockIdx.x * 256 + threadIdx.x) * 4;
    float4 v = *(const float4*)(in + i);
    __nv_bfloat16 h0 = __float2bfloat16(v.x), h1 = __float2bfloat16(v.y);
    __nv_bfloat16 h2 = __float2bfloat16(v.z), h3 = __float2bfloat16(v.w);
    __nv_bfloat162 hh0; hh0.x = h0; hh0.y = h1;
    __nv_bfloat162 hh1; hh1.x = h2; hh1.y = h3;
    *(__nv_bfloat162*)(oh + i)     = hh0;
    *(__nv_bfloat162*)(oh + i + 2) = hh1;
    __nv_bfloat162 ll0, ll1;
    ll0.x = __float2bfloat16(v.x - __bfloat162float(h0));
    ll0.y = __float2bfloat16(v.y - __bfloat162float(h1));
    ll1.x = __float2bfloat16(v.z - __bfloat162float(h2));
    ll1.y = __float2bfloat16(v.w - __bfloat162float(h3));
    *(__nv_bfloat162*)(ol + i)     = ll0;
    *(__nv_bfloat162*)(ol + i + 2) = ll1;
}

// ---------------- transpose + split: W[K=768][N] -> out[N][768] ------------
__global__ __launch_bounds__(256)
void k_splitT(const float* __restrict__ W, __nv_bfloat16* __restrict__ oh,
              __nv_bfloat16* __restrict__ ol, int Ncols)
{
    __shared__ float t[32][33];
    const int k0 = blockIdx.y * 32, n0 = blockIdx.x * 32;
    const int tx = threadIdx.x & 31, ty = threadIdx.x >> 5;
#pragma unroll
    for (int j = 0; j < 32; j += 8)
        t[ty + j][tx] = W[(size_t)(k0 + ty + j) * Ncols + n0 + tx];
    __syncthreads();
#pragma unroll
    for (int j = 0; j < 32; j += 8) {
        const float v = t[tx][ty + j];
        const __nv_bfloat16 h = __float2bfloat16(v);
        const size_t o = (size_t)(n0 + ty + j) * 768 + k0 + tx;
        oh[o] = h;
        ol[o] = __float2bfloat16(v - __bfloat162float(h));
    }
}

// ---------------- HMMA bf16x3 GEMM: 128x128 tiles, K=768 -------------------
#define PITCH   40
#define TILEB   (128 * PITCH * 2)
#define BUFB    (4 * TILEB)
#define GSMEM2  (2 * BUFB)
#define NCHUNK  24

template<int QKV>
__global__ __launch_bounds__(256, 1)
void k_gemm(const __nv_bfloat16* __restrict__ Ah, const __nv_bfloat16* __restrict__ Al,
            const __nv_bfloat16* __restrict__ Bh, const __nv_bfloat16* __restrict__ Bl,
            const float* __restrict__ bias, float* __restrict__ outp)
{
    extern __shared__ char smem[];
    const uint32_t sb = smem_u32(smem);
    const int tid = threadIdx.x;
    const int wid = tid >> 5, lane = tid & 31;
    const int m0 = blockIdx.y * 128, n0 = blockIdx.x * 128;
    const int warp_m = (wid & 1) * 64, warp_n = (wid >> 1) * 32;

    const __nv_bfloat16* srcs[4] = {Ah, Al, Bh, Bl};

    auto issue_load = [&](int c) {
        const int k0 = c * 32;
        const uint32_t dbase = sb + (c & 1) * BUFB;
#pragma unroll
        for (int i = 0; i < 8; i++) {
            const int idx = tid + i * 256;
            const int tl = idx >> 9, w = idx & 511;
            const int r = w >> 2, c8 = w & 3;
            const int rb = (tl < 2) ? m0 : n0;
            cpasync16(dbase + tl * TILEB + r * 80 + c8 * 16,
                      srcs[tl] + (size_t)(rb + r) * 768 + k0 + c8 * 8);
        }
        CP_COMMIT();
    };

    float acc[4][4][4];
#pragma unroll
    for (int mf = 0; mf < 4; mf++)
#pragma unroll
        for (int nf = 0; nf < 4; nf++)
#pragma unroll
            for (int e = 0; e < 4; e++) acc[mf][nf][e] = 0.f;

    const int rowA = (lane & 7) | (((lane >> 3) & 1) << 3);
    const uint32_t laneA = (uint32_t)(warp_m + rowA) * 80 + ((lane >> 4) << 4);
    const int l2 = lane & 15;
    const uint32_t laneB = (uint32_t)(warp_n + (l2 & 7)) * 80 + ((l2 >> 3) << 4);

    issue_load(0);

    for (int c = 0; c < NCHUNK; c++) {
        if (c + 1 < NCHUNK) {
            issue_load(c + 1);
            asm volatile("cp.async.wait_group 1;" ::: "memory");
        } else {
            asm volatile("cp.async.wait_group 0;" ::: "memory");
        }
        __syncthreads();

        const uint32_t base = sb + (c & 1) * BUFB;
        const uint32_t sAh = base,          sAl = base + TILEB;
        const uint32_t sBh = base + 2*TILEB, sBl = base + 3*TILEB;

#pragma unroll
        for (int ks = 0; ks < 32; ks += 16) {
            uint32_t ah[4][4], al[4][4], bh[4][2], bl[4][2];
#pragma unroll
            for (int mf = 0; mf < 4; mf++) {
                ldsm4(ah[mf], sAh + mf * 1280 + ks * 2 + laneA);
                ldsm4(al[mf], sAl + mf * 1280 + ks * 2 + laneA);
            }
#pragma unroll
            for (int nf = 0; nf < 4; nf++) {
                ldsm2(bh[nf], sBh + nf * 640 + ks * 2 + laneB);
                ldsm2(bl[nf], sBl + nf * 640 + ks * 2 + laneB);
            }
#pragma unroll
            for (int mf = 0; mf < 4; mf++)
#pragma unroll
                for (int nf = 0; nf < 4; nf++) {
                    mma16816(acc[mf][nf], ah[mf], bh[nf]);
                    mma16816(acc[mf][nf], ah[mf], bl[nf]);
                    mma16816(acc[mf][nf], al[mf], bh[nf]);
                }
        }
        __syncthreads();
    }

    const int lr = lane >> 2, lc = (lane & 3) * 2;
#pragma unroll
    for (int mf = 0; mf < 4; mf++) {
#pragma unroll
        for (int half = 0; half < 2; half++) {
            const int m = m0 + warp_m + mf * 16 + lr + half * 8;
#pragma unroll
            for (int nf = 0; nf < 4; nf++) {
                const int n = n0 + warp_n + nf * 8 + lc;
                const float v0 = acc[mf][nf][half * 2 + 0] + bias[n];
                const float v1 = acc[mf][nf][half * 2 + 1] + bias[n + 1];
                if (QKV) {
                    const int b = m >> 10, t = m & 1023;
                    const int part = n / 768;
                    const int rem  = n - part * 768;
                    const int h = rem >> 6, d = rem & 63;
                    const __nv_bfloat16 h0 = __float2bfloat16(v0);
                    const __nv_bfloat16 l0 = __float2bfloat16(v0 - __bfloat162float(h0));
                    const __nv_bfloat16 h1 = __float2bfloat16(v1);
                    const __nv_bfloat16 l1 = __float2bfloat16(v1 - __bfloat162float(h1));
                    if (part < 2) {
                        const size_t o = ((size_t)((b * NH + h) * NT + t)) * ND + d;
                        __nv_bfloat162 hh; hh.x = h0; hh.y = h1;
                        __nv_bfloat162 ll; ll.x = l0; ll.y = l1;
                        if (part == 0) { *(__nv_bfloat162*)(g_qh + o) = hh; *(__nv_bfloat162*)(g_ql + o) = ll; }
                        else           { *(__nv_bfloat162*)(g_kh + o) = hh; *(__nv_bfloat162*)(g_kl + o) = ll; }
                    } else {
                        const size_t o = ((size_t)((b * NH + h) * ND + d)) * NT + t;
                        g_vth[o] = h0; g_vtl[o] = l0;
                        g_vth[o + NT] = h1; g_vtl[o + NT] = l1;
                    }
                } else {
                    float2 o; o.x = v0; o.y = v1;
                    *(float2*)(outp + (size_t)m * 768 + n) = o;
                }
            }
        }
    }
}

// ---------------- HMMA attention, pipelined, register-P --------------------
// smem: Q hi/lo (2x18432) | 2 stages of {K hi/lo 2x18432, Vt hi/lo 2x17408} | RS/INV
#define AQH   0
#define AQL   18432
#define ASTG  36864
#define STGSZ 71680          // KH +0, KL +18432, VH +36864, VL +54272
#define ARED  (ASTG + STGSZ) // reuse stage-1 K region post-loop for yacc reduce
#define ARS   180224
#define AINV  181248
#define SMEMA 181760

__global__ __launch_bounds__(256, 1)
void k_attn(const float* __restrict__ bias, const float* __restrict__ mask,
            float* __restrict__ attn)
{
    extern __shared__ char sa[];
    const uint32_t sb = smem_u32(sa);
    float* RS  = (float*)(sa + ARS);
    float* INV = (float*)(sa + AINV);

    const int tid = threadIdx.x;
    const int wid = tid >> 5, lane = tid & 31;
    const int warp_m = wid & 3, warp_n = wid >> 2;   // 4 x 2
    const int b = blockIdx.z, h = blockIdx.y;
    const int t0 = blockIdx.x * 128;
    const int bh = b * NH + h;

    const float SC2E = 0.18033688f;    // 0.125 * log2(e)
    const float L2E  = 1.44269504f;

    // Q tile load (hi+lo): group 0
#pragma unroll
    for (int i = 0; i < 4; i++) {
        const int idx = tid + i * 256;
        const int r = idx >> 3, c = idx & 7;
        const size_t src = (size_t)(bh * NT + t0 + r) * ND + c * 8;
        cpasync16(sb + AQH + r * 144 + c * 16, g_qh + src);
        cpasync16(sb + AQL + r * 144 + c * 16, g_ql + src);
    }
    CP_COMMIT();

    // K/V stage loader
    auto issue_kv = [&](int st) {
        const int s0 = st * 128;
        const uint32_t stg = sb + ASTG + (st & 1) * STGSZ;
#pragma unroll
        for (int i = 0; i < 16; i++) {
            const int idx = tid + i * 256;
            const int arr = idx >> 10, w = idx & 1023;
            if (arr < 2) {
                const int r = w >> 3, c = w & 7;
                const size_t src = (size_t)(bh * NT + s0 + r) * ND + c * 8;
                cpasync16(stg + arr * 18432 + r * 144 + c * 16,
                          (arr ? g_kl : g_kh) + src);
            } else {
                const int r = w >> 4, c = w & 15;
                const size_t src = (size_t)(bh * ND + r) * NT + s0 + c * 8;
                cpasync16(stg + 36864 + (arr - 2) * 17408 + r * 272 + c * 16,
                          (arr == 2 ? g_vth : g_vtl) + src);
            }
        }
        CP_COMMIT();
    };

    float yacc[2][8][4];
#pragma unroll
    for (int mf = 0; mf < 2; mf++)
#pragma unroll
        for (int nf = 0; nf < 8; nf++)
#pragma unroll
            for (int e = 0; e < 4; e++) yacc[mf][nf][e] = 0.f;
    float rsum[2][2] = {{0.f, 0.f}, {0.f, 0.f}};

    const int lr = lane >> 2, lc = (lane & 3) * 2;
    const int rowA = (lane & 7) | (((lane >> 3) & 1) << 3);
    const uint32_t colA16 = (lane >> 4) << 4;
    const int l2 = lane & 15;
    const uint32_t laneQ = (uint32_t)(warp_m * 32 + rowA) * 144 + colA16;
    const uint32_t laneK = (uint32_t)(warp_n * 64 + (l2 & 7)) * 144 + ((l2 >> 3) << 4);
    const uint32_t laneV = (uint32_t)(l2 & 7) * 272 + ((l2 >> 3) << 4) + warp_n * 128;

    issue_kv(0);

    for (int st = 0; st < 8; st++) {
        if (st + 1 < 8) {
            issue_kv(st + 1);
            asm volatile("cp.async.wait_group 1;" ::: "memory");
        } else {
            asm volatile("cp.async.wait_group 0;" ::: "memory");
        }
        __syncthreads();

        const int s0 = st * 128;
        const uint32_t stg = sb + ASTG + (st & 1) * STGSZ;
        const uint32_t sKH = stg, sKL = stg + 18432;
        const uint32_t sVH = stg + 36864, sVL = stg + 54272;

        // ---- S = Q K^T (3-term), warp tile 32t x 64s ----
        float sacc[2][8][4];
#pragma unroll
        for (int mf = 0; mf < 2; mf++)
#pragma unroll
            for (int nf = 0; nf < 8; nf++)
#pragma unroll
                for (int e = 0; e < 4; e++) sacc[mf][nf][e] = 0.f;

#pragma unroll
        for (int ks = 0; ks < 4; ks++) {
            uint32_t qh[2][4], ql[2][4], kh[8][2], kl[8][2];
#pragma unroll
            for (int mf = 0; mf < 2; mf++) {
                ldsm4(qh[mf], sb + AQH + laneQ + mf * 16 * 144 + ks * 32);
                ldsm4(ql[mf], sb + AQL + laneQ + mf * 16 * 144 + ks * 32);
            }
#pragma unroll
            for (int nf = 0; nf < 8; nf++) {
                ldsm2(kh[nf], sKH + laneK + nf * 8 * 144 + ks * 32);
                ldsm2(kl[nf], sKL + laneK + nf * 8 * 144 + ks * 32);
            }
#pragma unroll
            for (int mf = 0; mf < 2; mf++)
#pragma unroll
                for (int nf = 0; nf < 8; nf++) {
                    mma16816(sacc[mf][nf], qh[mf], kh[nf]);
                    mma16816(sacc[mf][nf], qh[mf], kl[nf]);
                    mma16816(sacc[mf][nf], ql[mf], kh[nf]);
                }
        }

        // ---- exp + attn store; keep p in sacc (fp32) ----
#pragma unroll
        for (int mf = 0; mf < 2; mf++)
#pragma unroll
            for (int half = 0; half < 2; half++) {
                const int t = t0 + warp_m * 32 + mf * 16 + lr + half * 8;
                const size_t brow = ((size_t)bh * NT + t) * NT;
                const size_t mrow = ((size_t)b  * NT + t) * NT;
#pragma unroll
                for (int nf = 0; nf < 8; nf++) {
                    const int s = s0 + warp_n * 64 + nf * 8 + lc;
                    const float2 bb = *(const float2*)(bias + brow + s);
                    const float2 mm = *(const float2*)(mask + mrow + s);
                    float ta = fmaf(sacc[mf][nf][half*2+0], SC2E, (bb.x + mm.x) * L2E);
                    float tb = fmaf(sacc[mf][nf][half*2+1], SC2E, (bb.y + mm.y) * L2E);
                    ta = fmaxf(ta, -126.f);
                    tb = fmaxf(tb, -126.f);
                    const float p0 = fexp2(ta);
                    const float p1 = fexp2(tb);
                    rsum[mf][half] += p0 + p1;
                    float2 pw; pw.x = p0; pw.y = p1;
                    *(float2*)(attn + brow + s) = pw;
                    sacc[mf][nf][half*2+0] = p0;
                    sacc[mf][nf][half*2+1] = p1;
                }
            }

        // ---- y += P V (3-term), P fragments built from sacc registers ----
        // warp k-range: its own 64 s-columns; all 64 d-columns (nf 0..7)
#pragma unroll
        for (int kc = 0; kc < 4; kc++) {
            uint32_t pah[2][4], pal[2][4];
#pragma unroll
            for (int mf = 0; mf < 2; mf++) {
#pragma unroll
                for (int q = 0; q < 4; q++) {
                    const int nf = 2 * kc + (q >> 1);       // q 0,1 -> tile 2kc; 2,3 -> 2kc+1
                    const int e0 = (q & 1) * 2;             // 0 -> c0,c1 ; 1 -> c2,c3
                    const float v0 = sacc[mf][nf][e0 + 0];
                    const float v1 = sacc[mf][nf][e0 + 1];
                    const float h0 = __bfloat162float(__float2bfloat16(v0));
                    const float h1 = __bfloat162float(__float2bfloat16(v1));
                    pah[mf][q] = pkbf2(h0, h1);
                    pal[mf][q] = pkbf2(v0 - h0, v1 - h1);
                }
            }
#pragma unroll
            for (int nf = 0; nf < 8; nf++) {
                uint32_t vh[2], vl[2];
                ldsm2(vh, sVH + laneV + nf * 8 * 272 + kc * 32);
                ldsm2(vl, sVL + laneV + nf * 8 * 272 + kc * 32);
#pragma unroll
                for (int mf = 0; mf < 2; mf++) {
                    mma16816(yacc[mf][nf], pah[mf], vh);
                    mma16816(yacc[mf][nf], pah[mf], vl);
                    mma16816(yacc[mf][nf], pal[mf], vh);
                }
            }
        }
        __syncthreads();   // reads of this stage done before its buffer is reloaded
    }

    // ---- rowsum reduce (quad lanes share a row; halves via smem) ----
#pragma unroll
    for (int mf = 0; mf < 2; mf++)
#pragma unroll
        for (int half = 0; half < 2; half++) {
            float r = rsum[mf][half];
            r += __shfl_xor_sync(0xffffffffu, r, 1);
            r += __shfl_xor_sync(0xffffffffu, r, 2);
            if ((lane & 3) == 0)
                RS[warp_n * 128 + warp_m * 32 + mf * 16 + lr + half * 8] = r;
        }
    __syncthreads();
    if (tid < 128) INV[tid] = 1.0f / (RS[tid] + RS[128 + tid]);
    __syncthreads();

    // ---- cross-warp yacc reduce (s-halves) + fused y hi/lo epilogue ----
    {
        float* red = (float*)(sa + ARED);   // 4 x 32t x 64d fp32
        if (warp_n == 1) {
#pragma unroll
            for (int mf = 0; mf < 2; mf++)
#pragma unroll
                for (int half = 0; half < 2; half++) {
                    const int r = mf * 16 + lr + half * 8;
#pragma unroll
                    for (int nf = 0; nf < 8; nf++) {
                        float2 o;
                        o.x = yacc[mf][nf][half*2+0];
                        o.y = yacc[mf][nf][half*2+1];
                        *(float2*)(red + (warp_m * 32 + r) * 64 + nf * 8 + lc) = o;
                    }
                }
        }
        __syncthreads();
        if (warp_n == 0) {
#pragma unroll
            for (int mf = 0; mf < 2; mf++)
#pragma unroll
                for (int half = 0; half < 2; half++) {
                    const int tr = warp_m * 32 + mf * 16 + lr + half * 8;
                    const float inv = INV[tr];
                    const int t = t0 + tr;
#pragma unroll
                    for (int nf = 0; nf < 8; nf++) {
                        const int d = nf * 8 + lc;
                        const float2 pp = *(const float2*)(red + tr * 64 + d);
                        const float v0 = (yacc[mf][nf][half*2+0] + pp.x) * inv;
                        const float v1 = (yacc[mf][nf][half*2+1] + pp.y) * inv;
                        const __nv_bfloat16 h0 = __float2bfloat16(v0);
                        const __nv_bfloat16 h1 = __float2bfloat16(v1);
                        __nv_bfloat162 hh; hh.x = h0; hh.y = h1;
                        __nv_bfloat162 ll;
                        ll.x = __float2bfloat16(v0 - __bfloat162float(h0));
                        ll.y = __float2bfloat16(v1 - __bfloat162float(h1));
                        const size_t o = ((size_t)b * NT + t) * NC + h * ND + d;
                        *(__nv_bfloat162*)(g_yhh + o) = hh;
                        *(__nv_bfloat162*)(g_yhl + o) = ll;
                    }
                }
        }
    }

    // ---- normalize attn rows in place (block-local, L2-hot) ----
    for (int e = tid; e < 128 * 256; e += 256) {
        const int r = e >> 8, c = (e & 255) * 4;
        const float inv = INV[r];
        float4* p4 = (float4*)(attn + ((size_t)bh * NT + t0 + r) * NT + c);
        float4 v = *p4;
        v.x *= inv; v.y *= inv; v.z *= inv; v.w *= inv;
        *p4 = v;
    }
}

// ---------------- launch ---------------------------------------------------
extern "C" void kernel_launch(void* const* d_in, const int* in_sizes, int n_in,
                              void* d_out, int out_size)
{
    const float* x     = (const float*)d_in[0];
    const float* mask  = (const float*)d_in[1];
    const float* bias  = (const float*)d_in[2];
    const float* Wqkv  = (const float*)d_in[3];
    const float* bqkv  = (const float*)d_in[4];
    const float* Wproj = (const float*)d_in[5];
    const float* bproj = (const float*)d_in[6];

    float* y    = (float*)d_out;
    float* attn = y + (size_t)NB * NT * NC;

    cudaFuncSetAttribute(k_attn,    cudaFuncAttributeMaxDynamicSharedMemorySize, SMEMA);
    cudaFuncSetAttribute(k_gemm<1>, cudaFuncAttributeMaxDynamicSharedMemorySize, GSMEM2);
    cudaFuncSetAttribute(k_gemm<0>, cudaFuncAttributeMaxDynamicSharedMemorySize, GSMEM2);

    __nv_bfloat16 *xh, *xl, *wqh, *wql, *wph, *wpl, *yhh, *yhl;
    cudaGetSymbolAddress((void**)&xh,  g_xh);  cudaGetSymbolAddress((void**)&xl,  g_xl);
    cudaGetSymbolAddress((void**)&wqh, g_wqh); cudaGetSymbolAddress((void**)&wql, g_wql);
    cudaGetSymbolAddress((void**)&wph, g_wph); cudaGetSymbolAddress((void**)&wpl, g_wpl);
    cudaGetSymbolAddress((void**)&yhh, g_yhh); cudaGetSymbolAddress((void**)&yhl, g_yhl);

    k_split <<<4096 * 768 / 1024, 256>>>(x, xh, xl);
    k_splitT<<<dim3(2304 / 32, 768 / 32), 256>>>(Wqkv, wqh, wql, 2304);
    k_splitT<<<dim3(768 / 32,  768 / 32), 256>>>(Wproj, wph, wpl, 768);

    k_gemm<1><<<dim3(2304 / 128, 4096 / 128), 256, GSMEM2>>>(xh, xl, wqh, wql, bqkv, nullptr);
    k_attn  <<<dim3(NT / 128, NH, NB), 256, SMEMA>>>(bias, mask, attn);
    k_gemm<0><<<dim3(768 / 128, 4096 / 128), 256, GSMEM2>>>(yhh, yhl, wph, wpl, bproj, y);
}

// round 16
// speedup vs baseline: 1.0655x; 1.0655x over previous
#include <cuda_runtime.h>
#include <cuda_bf16.h>
#include <cstdint>

#define NB 4
#define NT 1024
#define NC 768
#define NH 12
#define ND 64

// ---------------- scratch (device globals; no allocation allowed) ----------
// bf16 split operands
__device__ __nv_bfloat16 g_xh[4096*768],  g_xl[4096*768];
__device__ __nv_bfloat16 g_wqh[2304*768], g_wql[2304*768];   // W_qkv^T  [N][K]
__device__ __nv_bfloat16 g_wph[768*768],  g_wpl[768*768];    // W_proj^T [N][K]
__device__ __nv_bfloat16 g_yhh[4096*768], g_yhl[4096*768];   // y pre-proj hi/lo
// q,k: [b,h,t,d]; v transposed: [b,h,d,s]
__device__ __nv_bfloat16 g_qh[NB*NH*NT*ND], g_ql[NB*NH*NT*ND];
__device__ __nv_bfloat16 g_kh[NB*NH*NT*ND], g_kl[NB*NH*NT*ND];
__device__ __nv_bfloat16 g_vth[NB*NH*ND*NT], g_vtl[NB*NH*ND*NT];

// ===================== HMMA helpers (sm_80+ portable) ======================
__device__ __forceinline__ uint32_t smem_u32(const void* p) {
    uint32_t a;
    asm("{ .reg .u64 t; cvta.to.shared.u64 t, %1; cvt.u32.u64 %0, t; }" : "=r"(a) : "l"(p));
    return a;
}
__device__ __forceinline__ void ldsm4(uint32_t* r, uint32_t addr) {
    asm volatile("ldmatrix.sync.aligned.m8n8.x4.shared.b16 {%0,%1,%2,%3}, [%4];"
        : "=r"(r[0]), "=r"(r[1]), "=r"(r[2]), "=r"(r[3]) : "r"(addr));
}
__device__ __forceinline__ void ldsm2(uint32_t* r, uint32_t addr) {
    asm volatile("ldmatrix.sync.aligned.m8n8.x2.shared.b16 {%0,%1}, [%2];"
        : "=r"(r[0]), "=r"(r[1]) : "r"(addr));
}
__device__ __forceinline__ void mma16816(float* c, const uint32_t* a, const uint32_t* b) {
    asm volatile("mma.sync.aligned.m16n8k16.row.col.f32.bf16.bf16.f32 "
        "{%0,%1,%2,%3}, {%4,%5,%6,%7}, {%8,%9}, {%0,%1,%2,%3};"
        : "+f"(c[0]), "+f"(c[1]), "+f"(c[2]), "+f"(c[3])
        : "r"(a[0]), "r"(a[1]), "r"(a[2]), "r"(a[3]), "r"(b[0]), "r"(b[1]));
}
__device__ __forceinline__ void cpasync16(uint32_t dst, const void* src) {
    asm volatile("cp.async.cg.shared.global [%0], [%1], 16;" :: "r"(dst), "l"(src));
}
#define CP_COMMIT() asm volatile("cp.async.commit_group;" ::: "memory")

// fast exp2: magic round + deg-5 poly; t must be >= -126 (clamped by caller)
__device__ __forceinline__ float fexp2(float t) {
    const float magic = 12582912.0f;   // 1.5 * 2^23
    float r = t + magic;
    float f = t - (r - magic);
    float p = 0.00133335581f;
    p = fmaf(p, f, 0.00961812911f);
    p = fmaf(p, f, 0.0555041087f);
    p = fmaf(p, f, 0.240226507f);
    p = fmaf(p, f, 0.693147182f);
    p = fmaf(p, f, 1.0f);
    return __int_as_float(__float_as_int(p) + (__float_as_int(r) << 23));
}

// ---------------- split fp32 -> bf16 hi/lo (elementwise) -------------------
__global__ __launch_bounds__(256)
void k_split(const float* __restrict__ in, __nv_bfloat16* __restrict__ oh,
             __nv_bfloat16* __restrict__ ol)
{
    const int i = (blockIdx.x * 256 + threadIdx.x) * 4;
    float4 v = *(const float4*)(in + i);
    __nv_bfloat16 h0 = __float2bfloat16(v.x), h1 = __float2bfloat16(v.y);
    __nv_bfloat16 h2 = __float2bfloat16(v.z), h3 = __float2bfloat16(v.w);
    __nv_bfloat162 hh0; hh0.x = h0; hh0.y = h1;
    __nv_bfloat162 hh1; hh1.x = h2; hh1.y = h3;
    *(__nv_bfloat162*)(oh + i)     = hh0;
    *(__nv_bfloat162*)(oh + i + 2) = hh1;
    __nv_bfloat162 ll0, ll1;
    ll0.x = __float2bfloat16(v.x - __bfloat162float(h0));
    ll0.y = __float2bfloat16(v.y - __bfloat162float(h1));
    ll1.x = __float2bfloat16(v.z - __bfloat162float(h2));
    ll1.y = __float2bfloat16(v.w - __bfloat162float(h3));
    *(__nv_bfloat162*)(ol + i)     = ll0;
    *(__nv_bfloat162*)(ol + i + 2) = ll1;
}

// ---------------- transpose + split: W[K=768][N] -> out[N][768] ------------
__global__ __launch_bounds__(256)
void k_splitT(const float* __restrict__ W, __nv_bfloat16* __restrict__ oh,
              __nv_bfloat16* __restrict__ ol, int Ncols)
{
    __shared__ float t[32][33];
    const int k0 = blockIdx.y * 32, n0 = blockIdx.x * 32;
    const int tx = threadIdx.x & 31, ty = threadIdx.x >> 5;
#pragma unroll
    for (int j = 0; j < 32; j += 8)
        t[ty + j][tx] = W[(size_t)(k0 + ty + j) * Ncols + n0 + tx];
    __syncthreads();
#pragma unroll
    for (int j = 0; j < 32; j += 8) {
        const float v = t[tx][ty + j];
        const __nv_bfloat16 h = __float2bfloat16(v);
        const size_t o = (size_t)(n0 + ty + j) * 768 + k0 + tx;
        oh[o] = h;
        ol[o] = __float2bfloat16(v - __bfloat162float(h));
    }
}

// ---------------- HMMA bf16x3 GEMM: 128x128 tiles, K=768 -------------------
#define PITCH   40
#define TILEB   (128 * PITCH * 2)
#define BUFB    (4 * TILEB)
#define GSMEM2  (2 * BUFB)
#define NCHUNK  24

template<int QKV>
__global__ __launch_bounds__(256, 1)
void k_gemm(const __nv_bfloat16* __restrict__ Ah, const __nv_bfloat16* __restrict__ Al,
            const __nv_bfloat16* __restrict__ Bh, const __nv_bfloat16* __restrict__ Bl,
            const float* __restrict__ bias, float* __restrict__ outp)
{
    extern __shared__ char smem[];
    const uint32_t sb = smem_u32(smem);
    const int tid = threadIdx.x;
    const int wid = tid >> 5, lane = tid & 31;
    const int m0 = blockIdx.y * 128, n0 = blockIdx.x * 128;
    const int warp_m = (wid & 1) * 64, warp_n = (wid >> 1) * 32;

    const __nv_bfloat16* srcs[4] = {Ah, Al, Bh, Bl};

    auto issue_load = [&](int c) {
        const int k0 = c * 32;
        const uint32_t dbase = sb + (c & 1) * BUFB;
#pragma unroll
        for (int i = 0; i < 8; i++) {
            const int idx = tid + i * 256;
            const int tl = idx >> 9, w = idx & 511;
            const int r = w >> 2, c8 = w & 3;
            const int rb = (tl < 2) ? m0 : n0;
            cpasync16(dbase + tl * TILEB + r * 80 + c8 * 16,
                      srcs[tl] + (size_t)(rb + r) * 768 + k0 + c8 * 8);
        }
        CP_COMMIT();
    };

    float acc[4][4][4];
#pragma unroll
    for (int mf = 0; mf < 4; mf++)
#pragma unroll
        for (int nf = 0; nf < 4; nf++)
#pragma unroll
            for (int e = 0; e < 4; e++) acc[mf][nf][e] = 0.f;

    const int rowA = (lane & 7) | (((lane >> 3) & 1) << 3);
    const uint32_t laneA = (uint32_t)(warp_m + rowA) * 80 + ((lane >> 4) << 4);
    const int l2 = lane & 15;
    const uint32_t laneB = (uint32_t)(warp_n + (l2 & 7)) * 80 + ((l2 >> 3) << 4);

    issue_load(0);

    for (int c = 0; c < NCHUNK; c++) {
        if (c + 1 < NCHUNK) {
            issue_load(c + 1);
            asm volatile("cp.async.wait_group 1;" ::: "memory");
        } else {
            asm volatile("cp.async.wait_group 0;" ::: "memory");
        }
        __syncthreads();

        const uint32_t base = sb + (c & 1) * BUFB;
        const uint32_t sAh = base,          sAl = base + TILEB;
        const uint32_t sBh = base + 2*TILEB, sBl = base + 3*TILEB;

#pragma unroll
        for (int ks = 0; ks < 32; ks += 16) {
            uint32_t ah[4][4], al[4][4], bh[4][2], bl[4][2];
#pragma unroll
            for (int mf = 0; mf < 4; mf++) {
                ldsm4(ah[mf], sAh + mf * 1280 + ks * 2 + laneA);
                ldsm4(al[mf], sAl + mf * 1280 + ks * 2 + laneA);
            }
#pragma unroll
            for (int nf = 0; nf < 4; nf++) {
                ldsm2(bh[nf], sBh + nf * 640 + ks * 2 + laneB);
                ldsm2(bl[nf], sBl + nf * 640 + ks * 2 + laneB);
            }
#pragma unroll
            for (int mf = 0; mf < 4; mf++)
#pragma unroll
                for (int nf = 0; nf < 4; nf++) {
                    mma16816(acc[mf][nf], ah[mf], bh[nf]);
                    mma16816(acc[mf][nf], ah[mf], bl[nf]);
                    mma16816(acc[mf][nf], al[mf], bh[nf]);
                }
        }
        __syncthreads();
    }

    const int lr = lane >> 2, lc = (lane & 3) * 2;
#pragma unroll
    for (int mf = 0; mf < 4; mf++) {
#pragma unroll
        for (int half = 0; half < 2; half++) {
            const int m = m0 + warp_m + mf * 16 + lr + half * 8;
#pragma unroll
            for (int nf = 0; nf < 4; nf++) {
                const int n = n0 + warp_n + nf * 8 + lc;
                const float v0 = acc[mf][nf][half * 2 + 0] + bias[n];
                const float v1 = acc[mf][nf][half * 2 + 1] + bias[n + 1];
                if (QKV) {
                    const int b = m >> 10, t = m & 1023;
                    const int part = n / 768;
                    const int rem  = n - part * 768;
                    const int h = rem >> 6, d = rem & 63;
                    const __nv_bfloat16 h0 = __float2bfloat16(v0);
                    const __nv_bfloat16 l0 = __float2bfloat16(v0 - __bfloat162float(h0));
                    const __nv_bfloat16 h1 = __float2bfloat16(v1);
                    const __nv_bfloat16 l1 = __float2bfloat16(v1 - __bfloat162float(h1));
                    if (part < 2) {
                        const size_t o = ((size_t)((b * NH + h) * NT + t)) * ND + d;
                        __nv_bfloat162 hh; hh.x = h0; hh.y = h1;
                        __nv_bfloat162 ll; ll.x = l0; ll.y = l1;
                        if (part == 0) { *(__nv_bfloat162*)(g_qh + o) = hh; *(__nv_bfloat162*)(g_ql + o) = ll; }
                        else           { *(__nv_bfloat162*)(g_kh + o) = hh; *(__nv_bfloat162*)(g_kl + o) = ll; }
                    } else {
                        const size_t o = ((size_t)((b * NH + h) * ND + d)) * NT + t;
                        g_vth[o] = h0; g_vtl[o] = l0;
                        g_vth[o + NT] = h1; g_vtl[o + NT] = l1;
                    }
                } else {
                    float2 o; o.x = v0; o.y = v1;
                    *(float2*)(outp + (size_t)m * 768 + n) = o;
                }
            }
        }
    }
}

// ---------------- HMMA attention (R10 skeleton + K double-buffer) ----------
// smem: Q hi/lo | K hi/lo x2 stages | V hi/lo | P hi/lo | RS | INV
#define AQH   0
#define AQL   18432
#define AKB   36864          // + buf*36864; KH +0, KL +18432
#define AVH   110592
#define AVL   128000
#define APH   145408
#define APL   180224
#define ARS   215040
#define AINV  216064
#define SMEMA 216576

__global__ __launch_bounds__(256, 1)
void k_attn(const float* __restrict__ bias, const float* __restrict__ mask,
            float* __restrict__ attn)
{
    extern __shared__ char sa[];
    const uint32_t sb = smem_u32(sa);
    float* RS  = (float*)(sa + ARS);
    float* INV = (float*)(sa + AINV);

    const int tid = threadIdx.x;
    const int wid = tid >> 5, lane = tid & 31;
    const int warp_m = wid & 3, warp_n = wid >> 2;   // 4 x 2
    const int b = blockIdx.z, h = blockIdx.y;
    const int t0 = blockIdx.x * 128;
    const int bh = b * NH + h;

    const float SC2E = 0.18033688f;    // 0.125 * log2(e)
    const float L2E  = 1.44269504f;

    // Q tile load (hi+lo): group 0
#pragma unroll
    for (int i = 0; i < 4; i++) {
        const int idx = tid + i * 256;
        const int r = idx >> 3, c = idx & 7;
        const size_t src = (size_t)(bh * NT + t0 + r) * ND + c * 8;
        cpasync16(sb + AQH + r * 144 + c * 16, g_qh + src);
        cpasync16(sb + AQL + r * 144 + c * 16, g_ql + src);
    }
    CP_COMMIT();

    // K stage loader (hi+lo, 2048 chunks)
    auto issue_k = [&](int st) {
        const int s0 = st * 128;
        const uint32_t kb = sb + AKB + (st & 1) * 36864;
#pragma unroll
        for (int i = 0; i < 8; i++) {
            const int idx = tid + i * 256;
            const int arr = idx >> 10, w = idx & 1023;
            const int r = w >> 3, c = w & 7;
            const size_t src = (size_t)(bh * NT + s0 + r) * ND + c * 8;
            cpasync16(kb + arr * 18432 + r * 144 + c * 16,
                      (arr ? g_kl : g_kh) + src);
        }
        CP_COMMIT();
    };
    // V stage loader (hi+lo, 2048 chunks) — single buffer
    auto issue_v = [&](int st) {
        const int s0 = st * 128;
#pragma unroll
        for (int i = 0; i < 8; i++) {
            const int idx = tid + i * 256;
            const int arr = idx >> 10, w = idx & 1023;
            const int r = w >> 4, c = w & 15;
            const size_t src = (size_t)(bh * ND + r) * NT + s0 + c * 8;
            cpasync16(sb + (arr ? AVL : AVH) + r * 272 + c * 16,
                      (arr ? g_vtl : g_vth) + src);
        }
        CP_COMMIT();
    };

    issue_k(0);
    issue_v(0);

    float yacc[2][4][4];
#pragma unroll
    for (int mf = 0; mf < 2; mf++)
#pragma unroll
        for (int nf = 0; nf < 4; nf++)
#pragma unroll
            for (int e = 0; e < 4; e++) yacc[mf][nf][e] = 0.f;
    float rsum[2][2] = {{0.f, 0.f}, {0.f, 0.f}};

    const int lr = lane >> 2, lc = (lane & 3) * 2;
    const int rowA = (lane & 7) | (((lane >> 3) & 1) << 3);
    const uint32_t colA16 = (lane >> 4) << 4;
    const int l2 = lane & 15;
    const uint32_t laneQ = (uint32_t)(warp_m * 32 + rowA) * 144 + colA16;
    const uint32_t laneK = (uint32_t)(warp_n * 64 + (l2 & 7)) * 144 + ((l2 >> 3) << 4);
    const uint32_t laneP = (uint32_t)(warp_m * 32 + rowA) * 272 + colA16;
    const uint32_t laneV = (uint32_t)(warp_n * 32 + (l2 & 7)) * 272 + ((l2 >> 3) << 4);

    for (int st = 0; st < 8; st++) {
        // prefetch next K into alternate buffer (its reads finished last stage)
        if (st + 1 < 8) {
            issue_k(st + 1);
            asm volatile("cp.async.wait_group 2;" ::: "memory");  // K(st) [+Q] done
        } else {
            asm volatile("cp.async.wait_group 1;" ::: "memory");  // allow only V(7)
        }
        __syncthreads();

        const int s0 = st * 128;
        const uint32_t kb = sb + AKB + (st & 1) * 36864;
        const uint32_t sKH = kb, sKL = kb + 18432;

        // ---- S = Q K^T (3-term), warp tile 32t x 64s ----
        float sacc[2][8][4];
#pragma unroll
        for (int mf = 0; mf < 2; mf++)
#pragma unroll
            for (int nf = 0; nf < 8; nf++)
#pragma unroll
                for (int e = 0; e < 4; e++) sacc[mf][nf][e] = 0.f;

#pragma unroll
        for (int ks = 0; ks < 4; ks++) {
            uint32_t qh[2][4], ql[2][4], kh[8][2], kl[8][2];
#pragma unroll
            for (int mf = 0; mf < 2; mf++) {
                ldsm4(qh[mf], sb + AQH + laneQ + mf * 16 * 144 + ks * 32);
                ldsm4(ql[mf], sb + AQL + laneQ + mf * 16 * 144 + ks * 32);
            }
#pragma unroll
            for (int nf = 0; nf < 8; nf++) {
                ldsm2(kh[nf], sKH + laneK + nf * 8 * 144 + ks * 32);
                ldsm2(kl[nf], sKL + laneK + nf * 8 * 144 + ks * 32);
            }
#pragma unroll
            for (int mf = 0; mf < 2; mf++)
#pragma unroll
                for (int nf = 0; nf < 8; nf++) {
                    mma16816(sacc[mf][nf], qh[mf], kh[nf]);
                    mma16816(sacc[mf][nf], qh[mf], kl[nf]);
                    mma16816(sacc[mf][nf], ql[mf], kh[nf]);
                }
        }

        // ---- exp, attn store, P -> smem (bf16 hi/lo), rowsum ----
#pragma unroll
        for (int mf = 0; mf < 2; mf++)
#pragma unroll
            for (int half = 0; half < 2; half++) {
                const int tr = warp_m * 32 + mf * 16 + lr + half * 8;
                const int t = t0 + tr;
                const size_t brow = ((size_t)bh * NT + t) * NT;
                const size_t mrow = ((size_t)b  * NT + t) * NT;
#pragma unroll
                for (int nf = 0; nf < 8; nf++) {
                    const int sc = warp_n * 64 + nf * 8 + lc;
                    const int s = s0 + sc;
                    const float2 bb = *(const float2*)(bias + brow + s);
                    const float2 mm = *(const float2*)(mask + mrow + s);
                    float ta = fmaf(sacc[mf][nf][half*2+0], SC2E, (bb.x + mm.x) * L2E);
                    float tb = fmaf(sacc[mf][nf][half*2+1], SC2E, (bb.y + mm.y) * L2E);
                    ta = fmaxf(ta, -126.f);
                    tb = fmaxf(tb, -126.f);
                    const float p0 = fexp2(ta);
                    const float p1 = fexp2(tb);
                    rsum[mf][half] += p0 + p1;
                    float2 pw; pw.x = p0; pw.y = p1;
                    *(float2*)(attn + brow + s) = pw;
                    const __nv_bfloat16 ph0 = __float2bfloat16(p0);
                    const __nv_bfloat16 pl0 = __float2bfloat16(p0 - __bfloat162float(ph0));
                    const __nv_bfloat16 ph1 = __float2bfloat16(p1);
                    const __nv_bfloat16 pl1 = __float2bfloat16(p1 - __bfloat162float(ph1));
                    __nv_bfloat162 hh; hh.x = ph0; hh.y = ph1;
                    __nv_bfloat162 ll; ll.x = pl0; ll.y = pl1;
                    *(__nv_bfloat162*)(sa + APH + tr * 272 + sc * 2) = hh;
                    *(__nv_bfloat162*)(sa + APL + tr * 272 + sc * 2) = ll;
                }
            }

        // V(st) must have landed; only K(st+1) may still be in flight
        if (st + 1 < 8) {
            asm volatile("cp.async.wait_group 1;" ::: "memory");
        } else {
            asm volatile("cp.async.wait_group 0;" ::: "memory");
        }
        __syncthreads();

        // ---- y += P V (3-term), warp tile 32t x 32d, k = full 128 s ----
#pragma unroll
        for (int ks = 0; ks < 8; ks++) {
            uint32_t ph[2][4], pl[2][4], vh[4][2], vl[4][2];
#pragma unroll
            for (int mf = 0; mf < 2; mf++) {
                ldsm4(ph[mf], sb + APH + laneP + mf * 16 * 272 + ks * 32);
                ldsm4(pl[mf], sb + APL + laneP + mf * 16 * 272 + ks * 32);
            }
#pragma unroll
            for (int nf = 0; nf < 4; nf++) {
                ldsm2(vh[nf], sb + AVH + laneV + nf * 8 * 272 + ks * 32);
                ldsm2(vl[nf], sb + AVL + laneV + nf * 8 * 272 + ks * 32);
            }
#pragma unroll
            for (int mf = 0; mf < 2; mf++)
#pragma unroll
                for (int nf = 0; nf < 4; nf++) {
                    mma16816(yacc[mf][nf], ph[mf], vh[nf]);
                    mma16816(yacc[mf][nf], ph[mf], vl[nf]);
                    mma16816(yacc[mf][nf], pl[mf], vh[nf]);
                }
        }
        __syncthreads();   // V/P reads done before next stage overwrites them

        // prefetch next V into the (now free) single V buffer
        if (st + 1 < 8) issue_v(st + 1);
    }

    // ---- rowsum reduce: quad lanes share a row ----
#pragma unroll
    for (int mf = 0; mf < 2; mf++)
#pragma unroll
        for (int half = 0; half < 2; half++) {
            float r = rsum[mf][half];
            r += __shfl_xor_sync(0xffffffffu, r, 1);
            r += __shfl_xor_sync(0xffffffffu, r, 2);
            if ((lane & 3) == 0)
                RS[warp_n * 128 + warp_m * 32 + mf * 16 + lr + half * 8] = r;
        }
    __syncthreads();
    if (tid < 128) INV[tid] = 1.0f / (RS[tid] + RS[128 + tid]);
    __syncthreads();

    // ---- y epilogue: fused hi/lo split, written directly for proj ----
#pragma unroll
    for (int mf = 0; mf < 2; mf++)
#pragma unroll
        for (int half = 0; half < 2; half++) {
            const int tr = warp_m * 32 + mf * 16 + lr + half * 8;
            const float inv = INV[tr];
            const int t = t0 + tr;
#pragma unroll
            for (int nf = 0; nf < 4; nf++) {
                const int d = warp_n * 32 + nf * 8 + lc;
                const float v0 = yacc[mf][nf][half*2+0] * inv;
                const float v1 = yacc[mf][nf][half*2+1] * inv;
                const __nv_bfloat16 h0 = __float2bfloat16(v0);
                const __nv_bfloat16 h1 = __float2bfloat16(v1);
                __nv_bfloat162 hh; hh.x = h0; hh.y = h1;
                __nv_bfloat162 ll;
                ll.x = __float2bfloat16(v0 - __bfloat162float(h0));
                ll.y = __float2bfloat16(v1 - __bfloat162float(h1));
                const size_t o = ((size_t)b * NT + t) * NC + h * ND + d;
                *(__nv_bfloat162*)(g_yhh + o) = hh;
                *(__nv_bfloat162*)(g_yhl + o) = ll;
            }
        }

    // ---- normalize attn rows in place (block-local, L2-hot) ----
    for (int e = tid; e < 128 * 256; e += 256) {
        const int r = e >> 8, c = (e & 255) * 4;
        const float inv = INV[r];
        float4* p4 = (float4*)(attn + ((size_t)bh * NT + t0 + r) * NT + c);
        float4 v = *p4;
        v.x *= inv; v.y *= inv; v.z *= inv; v.w *= inv;
        *p4 = v;
    }
}

// ---------------- launch ---------------------------------------------------
extern "C" void kernel_launch(void* const* d_in, const int* in_sizes, int n_in,
                              void* d_out, int out_size)
{
    const float* x     = (const float*)d_in[0];
    const float* mask  = (const float*)d_in[1];
    const float* bias  = (const float*)d_in[2];
    const float* Wqkv  = (const float*)d_in[3];
    const float* bqkv  = (const float*)d_in[4];
    const float* Wproj = (const float*)d_in[5];
    const float* bproj = (const float*)d_in[6];

    float* y    = (float*)d_out;
    float* attn = y + (size_t)NB * NT * NC;

    cudaFuncSetAttribute(k_attn,    cudaFuncAttributeMaxDynamicSharedMemorySize, SMEMA);
    cudaFuncSetAttribute(k_gemm<1>, cudaFuncAttributeMaxDynamicSharedMemorySize, GSMEM2);
    cudaFuncSetAttribute(k_gemm<0>, cudaFuncAttributeMaxDynamicSharedMemorySize, GSMEM2);

    __nv_bfloat16 *xh, *xl, *wqh, *wql, *wph, *wpl, *yhh, *yhl;
    cudaGetSymbolAddress((void**)&xh,  g_xh);  cudaGetSymbolAddress((void**)&xl,  g_xl);
    cudaGetSymbolAddress((void**)&wqh, g_wqh); cudaGetSymbolAddress((void**)&wql, g_wql);
    cudaGetSymbolAddress((void**)&wph, g_wph); cudaGetSymbolAddress((void**)&wpl, g_wpl);
    cudaGetSymbolAddress((void**)&yhh, g_yhh); cudaGetSymbolAddress((void**)&yhl, g_yhl);

    k_split <<<4096 * 768 / 1024, 256>>>(x, xh, xl);
    k_splitT<<<dim3(2304 / 32, 768 / 32), 256>>>(Wqkv, wqh, wql, 2304);
    k_splitT<<<dim3(768 / 32,  768 / 32), 256>>>(Wproj, wph, wpl, 768);

    k_gemm<1><<<dim3(2304 / 128, 4096 / 128), 256, GSMEM2>>>(xh, xl, wqh, wql, bqkv, nullptr);
    k_attn  <<<dim3(NT / 128, NH, NB), 256, SMEMA>>>(bias, mask, attn);
    k_gemm<0><<<dim3(768 / 128, 4096 / 128), 256, GSMEM2>>>(yhh, yhl, wph, wpl, bproj, y);
}

// round 17
// speedup vs baseline: 1.1042x; 1.0363x over previous
#include <cuda_runtime.h>
#include <cuda_bf16.h>
#include <cstdint>

#define NB 4
#define NT 1024
#define NC 768
#define NH 12
#define ND 64

// ---------------- scratch (device globals; no allocation allowed) ----------
// bf16 split operands
__device__ __nv_bfloat16 g_xh[4096*768],  g_xl[4096*768];
__device__ __nv_bfloat16 g_wqh[2304*768], g_wql[2304*768];   // W_qkv^T  [N][K]
__device__ __nv_bfloat16 g_wph[768*768],  g_wpl[768*768];    // W_proj^T [N][K]
__device__ __nv_bfloat16 g_yhh[4096*768], g_yhl[4096*768];   // y pre-proj hi/lo
// q,k: [b,h,t,d]; v transposed: [b,h,d,s]
__device__ __nv_bfloat16 g_qh[NB*NH*NT*ND], g_ql[NB*NH*NT*ND];
__device__ __nv_bfloat16 g_kh[NB*NH*NT*ND], g_kl[NB*NH*NT*ND];
__device__ __nv_bfloat16 g_vth[NB*NH*ND*NT], g_vtl[NB*NH*ND*NT];

// ===================== HMMA helpers (sm_80+ portable) ======================
__device__ __forceinline__ uint32_t smem_u32(const void* p) {
    uint32_t a;
    asm("{ .reg .u64 t; cvta.to.shared.u64 t, %1; cvt.u32.u64 %0, t; }" : "=r"(a) : "l"(p));
    return a;
}
__device__ __forceinline__ void ldsm4(uint32_t* r, uint32_t addr) {
    asm volatile("ldmatrix.sync.aligned.m8n8.x4.shared.b16 {%0,%1,%2,%3}, [%4];"
        : "=r"(r[0]), "=r"(r[1]), "=r"(r[2]), "=r"(r[3]) : "r"(addr));
}
__device__ __forceinline__ void ldsm2(uint32_t* r, uint32_t addr) {
    asm volatile("ldmatrix.sync.aligned.m8n8.x2.shared.b16 {%0,%1}, [%2];"
        : "=r"(r[0]), "=r"(r[1]) : "r"(addr));
}
__device__ __forceinline__ void mma16816(float* c, const uint32_t* a, const uint32_t* b) {
    asm volatile("mma.sync.aligned.m16n8k16.row.col.f32.bf16.bf16.f32 "
        "{%0,%1,%2,%3}, {%4,%5,%6,%7}, {%8,%9}, {%0,%1,%2,%3};"
        : "+f"(c[0]), "+f"(c[1]), "+f"(c[2]), "+f"(c[3])
        : "r"(a[0]), "r"(a[1]), "r"(a[2]), "r"(a[3]), "r"(b[0]), "r"(b[1]));
}
__device__ __forceinline__ void cpasync16(uint32_t dst, const void* src) {
    asm volatile("cp.async.cg.shared.global [%0], [%1], 16;" :: "r"(dst), "l"(src));
}
#define CP_COMMIT() asm volatile("cp.async.commit_group;" ::: "memory")

// fast exp2: magic round + deg-5 poly; t must be >= -126 (clamped by caller)
__device__ __forceinline__ float fexp2(float t) {
    const float magic = 12582912.0f;   // 1.5 * 2^23
    float r = t + magic;
    float f = t - (r - magic);
    float p = 0.00133335581f;
    p = fmaf(p, f, 0.00961812911f);
    p = fmaf(p, f, 0.0555041087f);
    p = fmaf(p, f, 0.240226507f);
    p = fmaf(p, f, 0.693147182f);
    p = fmaf(p, f, 1.0f);
    return __int_as_float(__float_as_int(p) + (__float_as_int(r) << 23));
}

// ---------------- split fp32 -> bf16 hi/lo (elementwise) -------------------
__global__ __launch_bounds__(256)
void k_split(const float* __restrict__ in, __nv_bfloat16* __restrict__ oh,
             __nv_bfloat16* __restrict__ ol)
{
    const int i = (blockIdx.x * 256 + threadIdx.x) * 4;
    float4 v = *(const float4*)(in + i);
    __nv_bfloat16 h0 = __float2bfloat16(v.x), h1 = __float2bfloat16(v.y);
    __nv_bfloat16 h2 = __float2bfloat16(v.z), h3 = __float2bfloat16(v.w);
    __nv_bfloat162 hh0; hh0.x = h0; hh0.y = h1;
    __nv_bfloat162 hh1; hh1.x = h2; hh1.y = h3;
    *(__nv_bfloat162*)(oh + i)     = hh0;
    *(__nv_bfloat162*)(oh + i + 2) = hh1;
    __nv_bfloat162 ll0, ll1;
    ll0.x = __float2bfloat16(v.x - __bfloat162float(h0));
    ll0.y = __float2bfloat16(v.y - __bfloat162float(h1));
    ll1.x = __float2bfloat16(v.z - __bfloat162float(h2));
    ll1.y = __float2bfloat16(v.w - __bfloat162float(h3));
    *(__nv_bfloat162*)(ol + i)     = ll0;
    *(__nv_bfloat162*)(ol + i + 2) = ll1;
}

// ---------------- transpose + split: W[K=768][N] -> out[N][768] ------------
__global__ __launch_bounds__(256)
void k_splitT(const float* __restrict__ W, __nv_bfloat16* __restrict__ oh,
              __nv_bfloat16* __restrict__ ol, int Ncols)
{
    __shared__ float t[32][33];
    const int k0 = blockIdx.y * 32, n0 = blockIdx.x * 32;
    const int tx = threadIdx.x & 31, ty = threadIdx.x >> 5;
#pragma unroll
    for (int j = 0; j < 32; j += 8)
        t[ty + j][tx] = W[(size_t)(k0 + ty + j) * Ncols + n0 + tx];
    __syncthreads();
#pragma unroll
    for (int j = 0; j < 32; j += 8) {
        const float v = t[tx][ty + j];
        const __nv_bfloat16 h = __float2bfloat16(v);
        const size_t o = (size_t)(n0 + ty + j) * 768 + k0 + tx;
        oh[o] = h;
        ol[o] = __float2bfloat16(v - __bfloat162float(h));
    }
}

// ------- HMMA bf16x3 GEMM: 256x128 CTA tile, 64x64 warp tile, K=768 -------
// A[M][768] K-major (hi/lo), B[N][768] K-major (hi/lo).
// rows = 32 bf16 data in 80B pitch (ldsm conflict-free)
#define APIT  80
#define ATILE (256 * APIT)     // 20480 B per A operand (hi or lo)
#define BTILE (128 * APIT)     // 10240 B per B operand
#define BUF3  (2 * ATILE + 2 * BTILE)   // 61440
#define GSMEM3 (2 * BUF3)               // 122880
#define NCH3  24               // 768 / 32

template<int QKV>
__global__ __launch_bounds__(256, 1)
void k_gemm(const __nv_bfloat16* __restrict__ Ah, const __nv_bfloat16* __restrict__ Al,
            const __nv_bfloat16* __restrict__ Bh, const __nv_bfloat16* __restrict__ Bl,
            const float* __restrict__ bias, float* __restrict__ outp)
{
    extern __shared__ char smem[];
    const uint32_t sb = smem_u32(smem);
    const int tid = threadIdx.x;
    const int wid = tid >> 5, lane = tid & 31;
    const int m0 = blockIdx.y * 256, n0 = blockIdx.x * 128;
    const int warp_m = (wid & 3) * 64, warp_n = (wid >> 2) * 64;

    // loader: 3072 cp16 per chunk, 12 per thread
    auto issue_load = [&](int c) {
        const int k0 = c * 32;
        const uint32_t dbase = sb + (c & 1) * BUF3;
#pragma unroll
        for (int i = 0; i < 12; i++) {
            const int idx = tid + i * 256;
            if (idx < 2048) {                 // A hi/lo
                const int hl = idx >> 10, w = idx & 1023;
                const int r = w >> 2, c4 = w & 3;
                cpasync16(dbase + hl * ATILE + r * APIT + c4 * 16,
                          (hl ? Al : Ah) + (size_t)(m0 + r) * 768 + k0 + c4 * 8);
            } else {                          // B hi/lo
                const int j = idx - 2048;
                const int hl = j >> 9, w = j & 511;
                const int r = w >> 2, c4 = w & 3;
                cpasync16(dbase + 2 * ATILE + hl * BTILE + r * APIT + c4 * 16,
                          (hl ? Bl : Bh) + (size_t)(n0 + r) * 768 + k0 + c4 * 8);
            }
        }
        CP_COMMIT();
    };

    float acc[4][8][4];
#pragma unroll
    for (int mf = 0; mf < 4; mf++)
#pragma unroll
        for (int nf = 0; nf < 8; nf++)
#pragma unroll
            for (int e = 0; e < 4; e++) acc[mf][nf][e] = 0.f;

    const int rowA = (lane & 7) | (((lane >> 3) & 1) << 3);
    const uint32_t laneA = (uint32_t)(warp_m + rowA) * APIT + ((lane >> 4) << 4);
    const int l2 = lane & 15;
    const uint32_t laneB = (uint32_t)(warp_n + (l2 & 7)) * APIT + ((l2 >> 3) << 4);

    issue_load(0);

    for (int c = 0; c < NCH3; c++) {
        if (c + 1 < NCH3) {
            issue_load(c + 1);
            asm volatile("cp.async.wait_group 1;" ::: "memory");
        } else {
            asm volatile("cp.async.wait_group 0;" ::: "memory");
        }
        __syncthreads();

        const uint32_t base = sb + (c & 1) * BUF3;
        const uint32_t sAh = base,             sAl = base + ATILE;
        const uint32_t sBh = base + 2 * ATILE, sBl = sBh + BTILE;

#pragma unroll
        for (int ks = 0; ks < 2; ks++) {
            uint32_t ah[4][4], al[4][4], bh[8][2], bl[8][2];
#pragma unroll
            for (int mf = 0; mf < 4; mf++) {
                ldsm4(ah[mf], sAh + laneA + mf * 16 * APIT + ks * 32);
                ldsm4(al[mf], sAl + laneA + mf * 16 * APIT + ks * 32);
            }
#pragma unroll
            for (int nf = 0; nf < 8; nf++) {
                ldsm2(bh[nf], sBh + laneB + nf * 8 * APIT + ks * 32);
                ldsm2(bl[nf], sBl + laneB + nf * 8 * APIT + ks * 32);
            }
#pragma unroll
            for (int mf = 0; mf < 4; mf++)
#pragma unroll
                for (int nf = 0; nf < 8; nf++) {
                    mma16816(acc[mf][nf], ah[mf], bh[nf]);
                    mma16816(acc[mf][nf], ah[mf], bl[nf]);
                    mma16816(acc[mf][nf], al[mf], bh[nf]);
                }
        }
        __syncthreads();
    }

    const int lr = lane >> 2, lc = (lane & 3) * 2;
#pragma unroll
    for (int mf = 0; mf < 4; mf++) {
#pragma unroll
        for (int half = 0; half < 2; half++) {
            const int m = m0 + warp_m + mf * 16 + lr + half * 8;
#pragma unroll
            for (int nf = 0; nf < 8; nf++) {
                const int n = n0 + warp_n + nf * 8 + lc;
                const float v0 = acc[mf][nf][half * 2 + 0] + bias[n];
                const float v1 = acc[mf][nf][half * 2 + 1] + bias[n + 1];
                if (QKV) {
                    const int b = m >> 10, t = m & 1023;
                    const int part = n / 768;
                    const int rem  = n - part * 768;
                    const int h = rem >> 6, d = rem & 63;
                    const __nv_bfloat16 h0 = __float2bfloat16(v0);
                    const __nv_bfloat16 l0 = __float2bfloat16(v0 - __bfloat162float(h0));
                    const __nv_bfloat16 h1 = __float2bfloat16(v1);
                    const __nv_bfloat16 l1 = __float2bfloat16(v1 - __bfloat162float(h1));
                    if (part < 2) {
                        const size_t o = ((size_t)((b * NH + h) * NT + t)) * ND + d;
                        __nv_bfloat162 hh; hh.x = h0; hh.y = h1;
                        __nv_bfloat162 ll; ll.x = l0; ll.y = l1;
                        if (part == 0) { *(__nv_bfloat162*)(g_qh + o) = hh; *(__nv_bfloat162*)(g_ql + o) = ll; }
                        else           { *(__nv_bfloat162*)(g_kh + o) = hh; *(__nv_bfloat162*)(g_kl + o) = ll; }
                    } else {
                        const size_t o = ((size_t)((b * NH + h) * ND + d)) * NT + t;
                        g_vth[o] = h0; g_vtl[o] = l0;
                        g_vth[o + NT] = h1; g_vtl[o + NT] = l1;
                    }
                } else {
                    float2 o; o.x = v0; o.y = v1;
                    *(float2*)(outp + (size_t)m * 768 + n) = o;
                }
            }
        }
    }
}

// ---------------- HMMA attention (R16, unchanged) --------------------------
#define AQH   0
#define AQL   18432
#define AKB   36864          // + buf*36864; KH +0, KL +18432
#define AVH   110592
#define AVL   128000
#define APH   145408
#define APL   180224
#define ARS   215040
#define AINV  216064
#define SMEMA 216576

__global__ __launch_bounds__(256, 1)
void k_attn(const float* __restrict__ bias, const float* __restrict__ mask,
            float* __restrict__ attn)
{
    extern __shared__ char sa[];
    const uint32_t sb = smem_u32(sa);
    float* RS  = (float*)(sa + ARS);
    float* INV = (float*)(sa + AINV);

    const int tid = threadIdx.x;
    const int wid = tid >> 5, lane = tid & 31;
    const int warp_m = wid & 3, warp_n = wid >> 2;   // 4 x 2
    const int b = blockIdx.z, h = blockIdx.y;
    const int t0 = blockIdx.x * 128;
    const int bh = b * NH + h;

    const float SC2E = 0.18033688f;    // 0.125 * log2(e)
    const float L2E  = 1.44269504f;

#pragma unroll
    for (int i = 0; i < 4; i++) {
        const int idx = tid + i * 256;
        const int r = idx >> 3, c = idx & 7;
        const size_t src = (size_t)(bh * NT + t0 + r) * ND + c * 8;
        cpasync16(sb + AQH + r * 144 + c * 16, g_qh + src);
        cpasync16(sb + AQL + r * 144 + c * 16, g_ql + src);
    }
    CP_COMMIT();

    auto issue_k = [&](int st) {
        const int s0 = st * 128;
        const uint32_t kb = sb + AKB + (st & 1) * 36864;
#pragma unroll
        for (int i = 0; i < 8; i++) {
            const int idx = tid + i * 256;
            const int arr = idx >> 10, w = idx & 1023;
            const int r = w >> 3, c = w & 7;
            const size_t src = (size_t)(bh * NT + s0 + r) * ND + c * 8;
            cpasync16(kb + arr * 18432 + r * 144 + c * 16,
                      (arr ? g_kl : g_kh) + src);
        }
        CP_COMMIT();
    };
    auto issue_v = [&](int st) {
        const int s0 = st * 128;
#pragma unroll
        for (int i = 0; i < 8; i++) {
            const int idx = tid + i * 256;
            const int arr = idx >> 10, w = idx & 1023;
            const int r = w >> 4, c = w & 15;
            const size_t src = (size_t)(bh * ND + r) * NT + s0 + c * 8;
            cpasync16(sb + (arr ? AVL : AVH) + r * 272 + c * 16,
                      (arr ? g_vtl : g_vth) + src);
        }
        CP_COMMIT();
    };

    issue_k(0);
    issue_v(0);

    float yacc[2][4][4];
#pragma unroll
    for (int mf = 0; mf < 2; mf++)
#pragma unroll
        for (int nf = 0; nf < 4; nf++)
#pragma unroll
            for (int e = 0; e < 4; e++) yacc[mf][nf][e] = 0.f;
    float rsum[2][2] = {{0.f, 0.f}, {0.f, 0.f}};

    const int lr = lane >> 2, lc = (lane & 3) * 2;
    const int rowA = (lane & 7) | (((lane >> 3) & 1) << 3);
    const uint32_t colA16 = (lane >> 4) << 4;
    const int l2 = lane & 15;
    const uint32_t laneQ = (uint32_t)(warp_m * 32 + rowA) * 144 + colA16;
    const uint32_t laneK = (uint32_t)(warp_n * 64 + (l2 & 7)) * 144 + ((l2 >> 3) << 4);
    const uint32_t laneP = (uint32_t)(warp_m * 32 + rowA) * 272 + colA16;
    const uint32_t laneV = (uint32_t)(warp_n * 32 + (l2 & 7)) * 272 + ((l2 >> 3) << 4);

    for (int st = 0; st < 8; st++) {
        if (st + 1 < 8) {
            issue_k(st + 1);
            asm volatile("cp.async.wait_group 2;" ::: "memory");
        } else {
            asm volatile("cp.async.wait_group 1;" ::: "memory");
        }
        __syncthreads();

        const int s0 = st * 128;
        const uint32_t kb = sb + AKB + (st & 1) * 36864;
        const uint32_t sKH = kb, sKL = kb + 18432;

        float sacc[2][8][4];
#pragma unroll
        for (int mf = 0; mf < 2; mf++)
#pragma unroll
            for (int nf = 0; nf < 8; nf++)
#pragma unroll
                for (int e = 0; e < 4; e++) sacc[mf][nf][e] = 0.f;

#pragma unroll
        for (int ks = 0; ks < 4; ks++) {
            uint32_t qh[2][4], ql[2][4], kh[8][2], kl[8][2];
#pragma unroll
            for (int mf = 0; mf < 2; mf++) {
                ldsm4(qh[mf], sb + AQH + laneQ + mf * 16 * 144 + ks * 32);
                ldsm4(ql[mf], sb + AQL + laneQ + mf * 16 * 144 + ks * 32);
            }
#pragma unroll
            for (int nf = 0; nf < 8; nf++) {
                ldsm2(kh[nf], sKH + laneK + nf * 8 * 144 + ks * 32);
                ldsm2(kl[nf], sKL + laneK + nf * 8 * 144 + ks * 32);
            }
#pragma unroll
            for (int mf = 0; mf < 2; mf++)
#pragma unroll
                for (int nf = 0; nf < 8; nf++) {
                    mma16816(sacc[mf][nf], qh[mf], kh[nf]);
                    mma16816(sacc[mf][nf], qh[mf], kl[nf]);
                    mma16816(sacc[mf][nf], ql[mf], kh[nf]);
                }
        }

#pragma unroll
        for (int mf = 0; mf < 2; mf++)
#pragma unroll
            for (int half = 0; half < 2; half++) {
                const int tr = warp_m * 32 + mf * 16 + lr + half * 8;
                const int t = t0 + tr;
                const size_t brow = ((size_t)bh * NT + t) * NT;
                const size_t mrow = ((size_t)b  * NT + t) * NT;
#pragma unroll
                for (int nf = 0; nf < 8; nf++) {
                    const int sc = warp_n * 64 + nf * 8 + lc;
                    const int s = s0 + sc;
                    const float2 bb = *(const float2*)(bias + brow + s);
                    const float2 mm = *(const float2*)(mask + mrow + s);
                    float ta = fmaf(sacc[mf][nf][half*2+0], SC2E, (bb.x + mm.x) * L2E);
                    float tb = fmaf(sacc[mf][nf][half*2+1], SC2E, (bb.y + mm.y) * L2E);
                    ta = fmaxf(ta, -126.f);
                    tb = fmaxf(tb, -126.f);
                    const float p0 = fexp2(ta);
                    const float p1 = fexp2(tb);
                    rsum[mf][half] += p0 + p1;
                    float2 pw; pw.x = p0; pw.y = p1;
                    *(float2*)(attn + brow + s) = pw;
                    const __nv_bfloat16 ph0 = __float2bfloat16(p0);
                    const __nv_bfloat16 pl0 = __float2bfloat16(p0 - __bfloat162float(ph0));
                    const __nv_bfloat16 ph1 = __float2bfloat16(p1);
                    const __nv_bfloat16 pl1 = __float2bfloat16(p1 - __bfloat162float(ph1));
                    __nv_bfloat162 hh; hh.x = ph0; hh.y = ph1;
                    __nv_bfloat162 ll; ll.x = pl0; ll.y = pl1;
                    *(__nv_bfloat162*)(sa + APH + tr * 272 + sc * 2) = hh;
                    *(__nv_bfloat162*)(sa + APL + tr * 272 + sc * 2) = ll;
                }
            }

        if (st + 1 < 8) {
            asm volatile("cp.async.wait_group 1;" ::: "memory");
        } else {
            asm volatile("cp.async.wait_group 0;" ::: "memory");
        }
        __syncthreads();

#pragma unroll
        for (int ks = 0; ks < 8; ks++) {
            uint32_t ph[2][4], pl[2][4], vh[4][2], vl[4][2];
#pragma unroll
            for (int mf = 0; mf < 2; mf++) {
                ldsm4(ph[mf], sb + APH + laneP + mf * 16 * 272 + ks * 32);
                ldsm4(pl[mf], sb + APL + laneP + mf * 16 * 272 + ks * 32);
            }
#pragma unroll
            for (int nf = 0; nf < 4; nf++) {
                ldsm2(vh[nf], sb + AVH + laneV + nf * 8 * 272 + ks * 32);
                ldsm2(vl[nf], sb + AVL + laneV + nf * 8 * 272 + ks * 32);
            }
#pragma unroll
            for (int mf = 0; mf < 2; mf++)
#pragma unroll
                for (int nf = 0; nf < 4; nf++) {
                    mma16816(yacc[mf][nf], ph[mf], vh[nf]);
                    mma16816(yacc[mf][nf], ph[mf], vl[nf]);
                    mma16816(yacc[mf][nf], pl[mf], vh[nf]);
                }
        }
        __syncthreads();

        if (st + 1 < 8) issue_v(st + 1);
    }

#pragma unroll
    for (int mf = 0; mf < 2; mf++)
#pragma unroll
        for (int half = 0; half < 2; half++) {
            float r = rsum[mf][half];
            r += __shfl_xor_sync(0xffffffffu, r, 1);
            r += __shfl_xor_sync(0xffffffffu, r, 2);
            if ((lane & 3) == 0)
                RS[warp_n * 128 + warp_m * 32 + mf * 16 + lr + half * 8] = r;
        }
    __syncthreads();
    if (tid < 128) INV[tid] = 1.0f / (RS[tid] + RS[128 + tid]);
    __syncthreads();

#pragma unroll
    for (int mf = 0; mf < 2; mf++)
#pragma unroll
        for (int half = 0; half < 2; half++) {
            const int tr = warp_m * 32 + mf * 16 + lr + half * 8;
            const float inv = INV[tr];
            const int t = t0 + tr;
#pragma unroll
            for (int nf = 0; nf < 4; nf++) {
                const int d = warp_n * 32 + nf * 8 + lc;
                const float v0 = yacc[mf][nf][half*2+0] * inv;
                const float v1 = yacc[mf][nf][half*2+1] * inv;
                const __nv_bfloat16 h0 = __float2bfloat16(v0);
                const __nv_bfloat16 h1 = __float2bfloat16(v1);
                __nv_bfloat162 hh; hh.x = h0; hh.y = h1;
                __nv_bfloat162 ll;
                ll.x = __float2bfloat16(v0 - __bfloat162float(h0));
                ll.y = __float2bfloat16(v1 - __bfloat162float(h1));
                const size_t o = ((size_t)b * NT + t) * NC + h * ND + d;
                *(__nv_bfloat162*)(g_yhh + o) = hh;
                *(__nv_bfloat162*)(g_yhl + o) = ll;
            }
        }

    for (int e = tid; e < 128 * 256; e += 256) {
        const int r = e >> 8, c = (e & 255) * 4;
        const float inv = INV[r];
        float4* p4 = (float4*)(attn + ((size_t)bh * NT + t0 + r) * NT + c);
        float4 v = *p4;
        v.x *= inv; v.y *= inv; v.z *= inv; v.w *= inv;
        *p4 = v;
    }
}

// ---------------- launch ---------------------------------------------------
extern "C" void kernel_launch(void* const* d_in, const int* in_sizes, int n_in,
                              void* d_out, int out_size)
{
    const float* x     = (const float*)d_in[0];
    const float* mask  = (const float*)d_in[1];
    const float* bias  = (const float*)d_in[2];
    const float* Wqkv  = (const float*)d_in[3];
    const float* bqkv  = (const float*)d_in[4];
    const float* Wproj = (const float*)d_in[5];
    const float* bproj = (const float*)d_in[6];

    float* y    = (float*)d_out;
    float* attn = y + (size_t)NB * NT * NC;

    cudaFuncSetAttribute(k_attn,    cudaFuncAttributeMaxDynamicSharedMemorySize, SMEMA);
    cudaFuncSetAttribute(k_gemm<1>, cudaFuncAttributeMaxDynamicSharedMemorySize, GSMEM3);
    cudaFuncSetAttribute(k_gemm<0>, cudaFuncAttributeMaxDynamicSharedMemorySize, GSMEM3);

    __nv_bfloat16 *xh, *xl, *wqh, *wql, *wph, *wpl, *yhh, *yhl;
    cudaGetSymbolAddress((void**)&xh,  g_xh);  cudaGetSymbolAddress((void**)&xl,  g_xl);
    cudaGetSymbolAddress((void**)&wqh, g_wqh); cudaGetSymbolAddress((void**)&wql, g_wql);
    cudaGetSymbolAddress((void**)&wph, g_wph); cudaGetSymbolAddress((void**)&wpl, g_wpl);
    cudaGetSymbolAddress((void**)&yhh, g_yhh); cudaGetSymbolAddress((void**)&yhl, g_yhl);

    k_split <<<4096 * 768 / 1024, 256>>>(x, xh, xl);
    k_splitT<<<dim3(2304 / 32, 768 / 32), 256>>>(Wqkv, wqh, wql, 2304);
    k_splitT<<<dim3(768 / 32,  768 / 32), 256>>>(Wproj, wph, wpl, 768);

    k_gemm<1><<<dim3(2304 / 128, 4096 / 256), 256, GSMEM3>>>(xh, xl, wqh, wql, bqkv, nullptr);
    k_attn  <<<dim3(NT / 128, NH, NB), 256, SMEMA>>>(bias, mask, attn);
    k_gemm<0><<<dim3(768 / 128, 4096 / 256), 256, GSMEM3>>>(yhh, yhl, wph, wpl, bproj, y);
}